// round 12
// baseline (speedup 1.0000x reference)
#include <cuda_runtime.h>
#include <cuda_bf16.h>

#define NSAMPLE 32
#define MAXN 8192
#define RADIUS2 1.0f
#define MAXCH 8   // max 32-lane chunks of K supported by the batched path (K<=256)

// Scratch (no allocations allowed)
__device__ int   g_ball[MAXN * NSAMPLE];
__device__ float g_delta[MAXN * NSAMPLE * 3];
__device__ int   g_cnt[MAXN];
__device__ int   g_off[MAXN + 1];
__device__ int   g_done = 0;

// sum of squares with explicit mul-then-left-assoc-add (no fma contraction),
// matching XLA's elementwise square + axis reduce.
__device__ __forceinline__ float sq3(float ax, float ay, float az) {
    return __fadd_rn(__fadd_rn(__fmul_rn(ax, ax), __fmul_rn(ay, ay)), __fmul_rn(az, az));
}

// ---------------------------------------------------------------------------
// Kernel 1: point blocks do fused roi-mask + ordered ball query (+ delta
// stash); zero blocks concurrently zero the ENTIRE output; the last block to
// finish performs the exclusive scan of counts.
// ---------------------------------------------------------------------------
__global__ void __launch_bounds__(256) query_zero_scan_kernel(
        const float* __restrict__ xyz,
        const float* __restrict__ new_xyz,
        const float* __restrict__ rois,
        float* __restrict__ out,            // whole output buffer (group+idx)
        int out_total,
        int N, int Nb, int M, int K,
        int point_blocks, int zero_blocks) {
    int lane = threadIdx.x & 31;
    int wid  = threadIdx.x >> 5;

    if ((int)blockIdx.x < point_blocks) {
        // ================= query: one warp per point =================
        int n = blockIdx.x * 8 + wid;
        if (n < N) {
            int b = n / Nb;
            float px = xyz[3 * n + 0], py = xyz[3 * n + 1], pz = xyz[3 * n + 2];

            // --- roi membership bitmask via per-lane checks + ballot ---
            const float* r = rois + (size_t)b * M * 7;
            unsigned long long bm = 0ull;
            for (int mb = 0; mb < M; mb += 32) {
                int m = mb + lane;
                bool in = false;
                if (m < M) {
                    float cx = r[m * 7 + 0], cy = r[m * 7 + 1], cz = r[m * 7 + 2];
                    float dx = r[m * 7 + 3], dy = r[m * 7 + 4], dz = r[m * 7 + 5];
                    float r2 = sq3(dx, dy, dz);
                    float d2 = sq3(__fsub_rn(px, cx), __fsub_rn(py, cy), __fsub_rn(pz, cz));
                    in = (d2 <= r2);
                }
                unsigned bits = __ballot_sync(0xffffffffu, in);
                bm |= ((unsigned long long)bits) << mb;
            }

            // --- ordered ball query: first NSAMPLE hits in j = m*K+k order ---
            int count = 0;
            int* outp = g_ball + n * NSAMPLE;
            float* dlp = g_delta + (size_t)n * NSAMPLE * 3;
            int baseMK = b * M * K;
            int nch = (K + 31) >> 5;

            if (nch <= MAXCH) {
                while (bm && count < NSAMPLE) {
                    int m = __ffsll((long long)bm) - 1;
                    bm &= bm - 1ull;
                    const float* g = new_xyz + ((size_t)(b * M + m)) * K * 3;

                    // batch-load ALL grid points for this roi (high MLP)
                    float gx[MAXCH], gy[MAXCH], gz[MAXCH];
                    #pragma unroll
                    for (int j = 0; j < MAXCH; j++) {
                        if (j < nch) {
                            int k = (j << 5) + lane;
                            int kc = k < K ? k : K - 1;     // clamp (masked later)
                            gx[j] = __ldg(&g[3 * kc + 0]);
                            gy[j] = __ldg(&g[3 * kc + 1]);
                            gz[j] = __ldg(&g[3 * kc + 2]);
                        }
                    }
                    // ballot loop entirely from registers
                    #pragma unroll
                    for (int j = 0; j < MAXCH; j++) {
                        if (j < nch && count < NSAMPLE) {
                            int k = (j << 5) + lane;
                            bool ok = false;
                            float ddx = 0.f, ddy = 0.f, ddz = 0.f;
                            if (k < K) {
                                ddx = __fsub_rn(px, gx[j]);
                                ddy = __fsub_rn(py, gy[j]);
                                ddz = __fsub_rn(pz, gz[j]);
                                float d2 = sq3(ddx, ddy, ddz);
                                ok = (d2 <= RADIUS2);
                            }
                            unsigned bits = __ballot_sync(0xffffffffu, ok);
                            int rank = count + __popc(bits & ((1u << lane) - 1u));
                            if (ok && rank < NSAMPLE) {
                                outp[rank] = baseMK + m * K + k;
                                float* dp = dlp + rank * 3;
                                dp[0] = ddx; dp[1] = ddy; dp[2] = ddz;
                            }
                            count += __popc(bits);
                        }
                    }
                }
            } else {
                // generic fallback (K > 32*MAXCH)
                while (bm && count < NSAMPLE) {
                    int m = __ffsll((long long)bm) - 1;
                    bm &= bm - 1ull;
                    const float* g = new_xyz + ((size_t)(b * M + m)) * K * 3;
                    for (int k0 = 0; k0 < K && count < NSAMPLE; k0 += 32) {
                        int k = k0 + lane;
                        bool ok = false;
                        float ddx = 0.f, ddy = 0.f, ddz = 0.f;
                        if (k < K) {
                            ddx = __fsub_rn(px, g[3 * k + 0]);
                            ddy = __fsub_rn(py, g[3 * k + 1]);
                            ddz = __fsub_rn(pz, g[3 * k + 2]);
                            float d2 = sq3(ddx, ddy, ddz);
                            ok = (d2 <= RADIUS2);
                        }
                        unsigned bits = __ballot_sync(0xffffffffu, ok);
                        int rank = count + __popc(bits & ((1u << lane) - 1u));
                        if (ok && rank < NSAMPLE) {
                            outp[rank] = baseMK + m * K + k;
                            float* dp = dlp + rank * 3;
                            dp[0] = ddx; dp[1] = ddy; dp[2] = ddz;
                        }
                        count += __popc(bits);
                    }
                }
            }
            if (lane == 0) g_cnt[n] = count < NSAMPLE ? count : NSAMPLE;
        }
    } else {
        // ================= zero: grid-stride over whole output =================
        int t = (blockIdx.x - point_blocks) * blockDim.x + threadIdx.x;
        int stride = zero_blocks * blockDim.x;
        float4 z4 = make_float4(0.f, 0.f, 0.f, 0.f);
        float4* o4 = (float4*)out;
        int n4 = out_total >> 2;
        for (int i = t; i < n4; i += stride) o4[i] = z4;
        for (int i = (n4 << 2) + t; i < out_total; i += stride) out[i] = 0.f;
    }

    // --- release fence, then last-block-done -> exclusive scan ---
    __threadfence();
    __shared__ int sh_isLast;
    __syncthreads();
    if (threadIdx.x == 0) {
        int t = atomicAdd(&g_done, 1);
        sh_isLast = (t == (int)gridDim.x - 1) ? 1 : 0;
    }
    __syncthreads();
    if (!sh_isLast) return;

    // scan of g_cnt[0..N) -> g_off (exclusive), g_off[N] = total. 256 threads.
    int tid = threadIdx.x;
    int per = (N + 255) / 256;           // <= 32 for MAXN=8192
    int base = tid * per;
    int loc[32];
    int s = 0;
    #pragma unroll 4
    for (int i = 0; i < per; i++) {
        int v = (base + i < N) ? __ldcg(&g_cnt[base + i]) : 0;
        loc[i] = v;
        s += v;
    }
    // warp inclusive scan of per-thread sums
    int pre = s;
    #pragma unroll
    for (int d = 1; d < 32; d <<= 1) {
        int t = __shfl_up_sync(0xffffffffu, pre, d);
        if (lane >= d) pre += t;
    }
    __shared__ int wsum[8];
    if (lane == 31) wsum[wid] = pre;
    __syncthreads();
    if (tid == 0) {
        int acc = 0;
        #pragma unroll
        for (int w = 0; w < 8; w++) { int t = wsum[w]; wsum[w] = acc; acc += t; }
    }
    __syncthreads();
    int run = wsum[wid] + (pre - s);     // exclusive prefix for this chunk
    #pragma unroll 4
    for (int i = 0; i < per; i++) {
        if (base + i < N) g_off[base + i] = run;
        run += loc[i];
    }
    if (tid == 255) g_off[N] = run;      // grand total (pads are zero)
    if (tid == 0) g_done = 0;            // reset for next graph replay
}

// ---------------------------------------------------------------------------
// Kernel 2 (specialized W=35, C=32): valid-row gather only. Warp per point.
// All inputs come from flat scratch (cnt/off/ball/delta) -> one parallel L2
// hop, then a burst of coalesced feature stores + tiny xyz fixup.
// ---------------------------------------------------------------------------
__global__ void __launch_bounds__(64) gather35_kernel(
        const float* __restrict__ feat,
        float* __restrict__ out_group,
        float* __restrict__ out_idx,
        int N, int has_idx) {
    const int W = 35, C = 32;
    int lane = threadIdx.x & 31;
    int n = blockIdx.x * 2 + (threadIdx.x >> 5);
    if (n >= N) return;
    int cnt = g_cnt[n];
    if (cnt == 0) return;
    int off = g_off[n];

    float fv = feat[(size_t)n * C + lane];          // C == 32: one per lane
    float dxl = 0.f, dyl = 0.f, dzl = 0.f;
    if (lane < cnt) {
        int gi = g_ball[n * NSAMPLE + lane];
        const float* dp = g_delta + ((size_t)n * NSAMPLE + lane) * 3;
        dxl = dp[0]; dyl = dp[1]; dzl = dp[2];
        if (has_idx) out_idx[off + lane] = (float)gi;
    }

    float* base = out_group + (size_t)off * W;      // contiguous span
    // feature block: one coalesced store per row, lane-resident value.
    float* p = base + 3 + lane;
    #pragma unroll 4
    for (int s = 0; s < cnt; s++) {
        *p = fv;
        p += W;
    }
    // residual fixup: lane s writes its row's 3 xyz deltas.
    if (lane < cnt) {
        float* r = base + lane * W;
        r[0] = dxl; r[1] = dyl; r[2] = dzl;
    }
}

// ---------------------------------------------------------------------------
// Generic fallback gather (any W/C): warp per slot, row-wise (rarely used).
// Output already zeroed by K1; writes only valid rows.
// ---------------------------------------------------------------------------
__global__ void __launch_bounds__(256) gather_generic_kernel(
        const float* __restrict__ xyz,
        const float* __restrict__ new_xyz,
        const float* __restrict__ feat,
        float* __restrict__ out_group,
        float* __restrict__ out_idx,
        int N, int C, int has_idx) {
    int gw   = (blockIdx.x * blockDim.x + threadIdx.x) >> 5;
    int lane = threadIdx.x & 31;
    int L = N * NSAMPLE;
    if (gw >= L) return;
    int W = 3 + C;

    int n = gw >> 5;
    int s = gw & (NSAMPLE - 1);
    if (s < g_cnt[n]) {
        int pos = g_off[n] + s;
        int gi  = g_ball[n * NSAMPLE + s];
        float* row = out_group + (size_t)pos * W;
        for (int c = lane; c < W; c += 32) {
            float v;
            if (c < 3) v = __fsub_rn(xyz[3 * n + c], new_xyz[3 * (size_t)gi + c]);
            else       v = feat[(size_t)n * C + (c - 3)];
            row[c] = v;
        }
        if (lane == 0 && has_idx) out_idx[pos] = (float)gi;
    }
}

// ---------------------------------------------------------------------------
extern "C" void kernel_launch(void* const* d_in, const int* in_sizes, int n_in,
                              void* d_out, int out_size) {
    const float* xyz      = (const float*)d_in[0];
    const float* new_xyz  = (const float*)d_in[2];
    const float* rois     = (const float*)d_in[3];
    const float* features = (const float*)d_in[4];

    int N  = in_sizes[0] / 3;
    int B  = in_sizes[1];
    int M  = in_sizes[3] / (7 * B);
    int K  = in_sizes[2] / (3 * B * M);
    int C  = in_sizes[4] / N;
    int Nb = N / B;
    int L  = N * NSAMPLE;
    int W  = 3 + C;

    float* out = (float*)d_out;
    int has_idx = (out_size >= L * W + L) ? 1 : 0;
    float* out_idx = out + (size_t)L * W;

    // 1. fused query (+delta stash) || full-output zero || last-block scan
    {
        int point_blocks = (N + 7) / 8;    // 8 warps per 256-thread block
        int zero_blocks  = 512;
        query_zero_scan_kernel<<<point_blocks + zero_blocks, 256>>>(
            xyz, new_xyz, rois, out, out_size,
            N, Nb, M, K, point_blocks, zero_blocks);
    }
    // 2. valid-row gather
    if (C == 32) {
        gather35_kernel<<<(N + 1) / 2, 64>>>(features, out, out_idx, N, has_idx);
    } else {
        int blocks = (L * 32 + 255) / 256;
        gather_generic_kernel<<<blocks, 256>>>(xyz, new_xyz, features, out, out_idx,
                                               N, C, has_idx);
    }
}

// round 14
// speedup vs baseline: 1.0947x; 1.0947x over previous
#include <cuda_runtime.h>
#include <cuda_bf16.h>

#define NSAMPLE 32
#define MAXN 8192
#define RADIUS2 1.0f
#define MAXCH 8   // max 32-lane chunks of K supported by the batched path (K<=256)

// Scratch (no allocations allowed)
__device__ int   g_ball[MAXN * NSAMPLE];
__device__ float g_delta[MAXN * NSAMPLE * 3];
__device__ int   g_cnt[MAXN];
__device__ int   g_off[MAXN + 1];
__device__ int   g_done = 0;

// sum of squares with explicit mul-then-left-assoc-add (no fma contraction),
// matching XLA's elementwise square + axis reduce.
__device__ __forceinline__ float sq3(float ax, float ay, float az) {
    return __fadd_rn(__fadd_rn(__fmul_rn(ax, ax), __fmul_rn(ay, ay)), __fmul_rn(az, az));
}

// ---------------------------------------------------------------------------
// Kernel 1: one warp per point. Fused roi-mask + ordered ball query (+delta
// stash), then EACH WARP zeroes its 1/nwarps slice of the whole output
// (overlap is structural: no extra blocks, no second wave). Last block to
// finish performs the exclusive scan of counts.
// ---------------------------------------------------------------------------
__global__ void __launch_bounds__(256) query_zero_scan_kernel(
        const float* __restrict__ xyz,
        const float* __restrict__ new_xyz,
        const float* __restrict__ rois,
        float* __restrict__ out,            // whole output buffer (group+idx)
        int out_total,
        int N, int Nb, int M, int K) {
    int lane = threadIdx.x & 31;
    int wid  = threadIdx.x >> 5;
    int n    = blockIdx.x * 8 + wid;
    int gw   = n;                            // global warp id
    int nwarps = gridDim.x * 8;

    if (n < N) {
        int b = n / Nb;
        float px = xyz[3 * n + 0], py = xyz[3 * n + 1], pz = xyz[3 * n + 2];

        // --- roi membership bitmask via per-lane checks + ballot ---
        const float* r = rois + (size_t)b * M * 7;
        unsigned long long bm = 0ull;
        for (int mb = 0; mb < M; mb += 32) {
            int m = mb + lane;
            bool in = false;
            if (m < M) {
                float cx = r[m * 7 + 0], cy = r[m * 7 + 1], cz = r[m * 7 + 2];
                float dx = r[m * 7 + 3], dy = r[m * 7 + 4], dz = r[m * 7 + 5];
                float r2 = sq3(dx, dy, dz);
                float d2 = sq3(__fsub_rn(px, cx), __fsub_rn(py, cy), __fsub_rn(pz, cz));
                in = (d2 <= r2);
            }
            unsigned bits = __ballot_sync(0xffffffffu, in);
            bm |= ((unsigned long long)bits) << mb;
        }

        // --- ordered ball query: first NSAMPLE hits in j = m*K+k order ---
        int count = 0;
        int* outp = g_ball + n * NSAMPLE;
        float* dlp = g_delta + (size_t)n * NSAMPLE * 3;
        int baseMK = b * M * K;
        int nch = (K + 31) >> 5;

        if (nch <= MAXCH) {
            while (bm && count < NSAMPLE) {
                int m = __ffsll((long long)bm) - 1;
                bm &= bm - 1ull;
                const float* g = new_xyz + ((size_t)(b * M + m)) * K * 3;

                // batch-load ALL grid points for this roi (high MLP)
                float gx[MAXCH], gy[MAXCH], gz[MAXCH];
                #pragma unroll
                for (int j = 0; j < MAXCH; j++) {
                    if (j < nch) {
                        int k = (j << 5) + lane;
                        int kc = k < K ? k : K - 1;     // clamp (masked later)
                        gx[j] = __ldg(&g[3 * kc + 0]);
                        gy[j] = __ldg(&g[3 * kc + 1]);
                        gz[j] = __ldg(&g[3 * kc + 2]);
                    }
                }
                // ballot loop entirely from registers
                #pragma unroll
                for (int j = 0; j < MAXCH; j++) {
                    if (j < nch && count < NSAMPLE) {
                        int k = (j << 5) + lane;
                        bool ok = false;
                        float ddx = 0.f, ddy = 0.f, ddz = 0.f;
                        if (k < K) {
                            ddx = __fsub_rn(px, gx[j]);
                            ddy = __fsub_rn(py, gy[j]);
                            ddz = __fsub_rn(pz, gz[j]);
                            float d2 = sq3(ddx, ddy, ddz);
                            ok = (d2 <= RADIUS2);
                        }
                        unsigned bits = __ballot_sync(0xffffffffu, ok);
                        int rank = count + __popc(bits & ((1u << lane) - 1u));
                        if (ok && rank < NSAMPLE) {
                            outp[rank] = baseMK + m * K + k;
                            float* dp = dlp + rank * 3;
                            dp[0] = ddx; dp[1] = ddy; dp[2] = ddz;
                        }
                        count += __popc(bits);
                    }
                }
            }
        } else {
            // generic fallback (K > 32*MAXCH)
            while (bm && count < NSAMPLE) {
                int m = __ffsll((long long)bm) - 1;
                bm &= bm - 1ull;
                const float* g = new_xyz + ((size_t)(b * M + m)) * K * 3;
                for (int k0 = 0; k0 < K && count < NSAMPLE; k0 += 32) {
                    int k = k0 + lane;
                    bool ok = false;
                    float ddx = 0.f, ddy = 0.f, ddz = 0.f;
                    if (k < K) {
                        ddx = __fsub_rn(px, g[3 * k + 0]);
                        ddy = __fsub_rn(py, g[3 * k + 1]);
                        ddz = __fsub_rn(pz, g[3 * k + 2]);
                        float d2 = sq3(ddx, ddy, ddz);
                        ok = (d2 <= RADIUS2);
                    }
                    unsigned bits = __ballot_sync(0xffffffffu, ok);
                    int rank = count + __popc(bits & ((1u << lane) - 1u));
                    if (ok && rank < NSAMPLE) {
                        outp[rank] = baseMK + m * K + k;
                        float* dp = dlp + rank * 3;
                        dp[0] = ddx; dp[1] = ddy; dp[2] = ddz;
                    }
                    count += __popc(bits);
                }
            }
        }
        if (lane == 0) g_cnt[n] = count < NSAMPLE ? count : NSAMPLE;
    }

    // ---- absorbed zero: each warp zeroes its slice of the whole output ----
    {
        float4 z4 = make_float4(0.f, 0.f, 0.f, 0.f);
        float4* o4 = (float4*)out;
        int n4 = out_total >> 2;
        int t = gw * 32 + lane;
        int stride = nwarps * 32;
        for (int i = t; i < n4; i += stride) o4[i] = z4;
        if (gw == 0) {
            int rem = out_total & 3;
            if (lane < rem) out[(n4 << 2) + lane] = 0.f;
        }
    }

    // --- release fence, then last-block-done -> exclusive scan ---
    __threadfence();
    __shared__ int sh_isLast;
    __syncthreads();
    if (threadIdx.x == 0) {
        int t = atomicAdd(&g_done, 1);
        sh_isLast = (t == (int)gridDim.x - 1) ? 1 : 0;
    }
    __syncthreads();
    if (!sh_isLast) return;

    // scan of g_cnt[0..N) -> g_off (exclusive), g_off[N] = total. 256 threads.
    int tid = threadIdx.x;
    int per = (N + 255) / 256;           // <= 32 for MAXN=8192
    int base = tid * per;
    int loc[32];
    int s = 0;
    #pragma unroll 4
    for (int i = 0; i < per; i++) {
        int v = (base + i < N) ? __ldcg(&g_cnt[base + i]) : 0;
        loc[i] = v;
        s += v;
    }
    // warp inclusive scan of per-thread sums
    int pre = s;
    #pragma unroll
    for (int d = 1; d < 32; d <<= 1) {
        int t = __shfl_up_sync(0xffffffffu, pre, d);
        if (lane >= d) pre += t;
    }
    __shared__ int wsum[8];
    if (lane == 31) wsum[wid] = pre;
    __syncthreads();
    if (tid == 0) {
        int acc = 0;
        #pragma unroll
        for (int w = 0; w < 8; w++) { int t = wsum[w]; wsum[w] = acc; acc += t; }
    }
    __syncthreads();
    int run = wsum[wid] + (pre - s);     // exclusive prefix for this chunk
    #pragma unroll 4
    for (int i = 0; i < per; i++) {
        if (base + i < N) g_off[base + i] = run;
        run += loc[i];
    }
    if (tid == 255) g_off[N] = run;      // grand total (pads are zero)
    if (tid == 0) g_done = 0;            // reset for next graph replay
}

// ---------------------------------------------------------------------------
// Kernel 2 (specialized W=35, C=32): valid-row gather only. One warp per
// point, 8 warps / 256-thr block. All inputs from flat scratch -> one
// parallel L2 hop, then a burst of coalesced feature stores + xyz fixup.
// ---------------------------------------------------------------------------
__global__ void __launch_bounds__(256) gather35_kernel(
        const float* __restrict__ feat,
        float* __restrict__ out_group,
        float* __restrict__ out_idx,
        int N, int has_idx) {
    const int W = 35, C = 32;
    int lane = threadIdx.x & 31;
    int n = blockIdx.x * 8 + (threadIdx.x >> 5);
    if (n >= N) return;
    int cnt = __ldg(&g_cnt[n]);
    if (cnt == 0) return;
    int off = __ldg(&g_off[n]);

    float fv = __ldg(&feat[(size_t)n * C + lane]);  // C == 32: one per lane
    float dxl = 0.f, dyl = 0.f, dzl = 0.f;
    if (lane < cnt) {
        int gi = __ldg(&g_ball[n * NSAMPLE + lane]);
        const float* dp = g_delta + ((size_t)n * NSAMPLE + lane) * 3;
        dxl = dp[0]; dyl = dp[1]; dzl = dp[2];
        if (has_idx) out_idx[off + lane] = (float)gi;
    }

    float* base = out_group + (size_t)off * W;      // contiguous span
    // feature block: one coalesced store per row, lane-resident value.
    float* p = base + 3 + lane;
    #pragma unroll 4
    for (int s = 0; s < cnt; s++) {
        *p = fv;
        p += W;
    }
    // residual fixup: lane s writes its row's 3 xyz deltas.
    if (lane < cnt) {
        float* r = base + lane * W;
        r[0] = dxl; r[1] = dyl; r[2] = dzl;
    }
}

// ---------------------------------------------------------------------------
// Generic fallback gather (any W/C): warp per slot, row-wise (rarely used).
// Output already zeroed by K1; writes only valid rows.
// ---------------------------------------------------------------------------
__global__ void __launch_bounds__(256) gather_generic_kernel(
        const float* __restrict__ xyz,
        const float* __restrict__ new_xyz,
        const float* __restrict__ feat,
        float* __restrict__ out_group,
        float* __restrict__ out_idx,
        int N, int C, int has_idx) {
    int gw   = (blockIdx.x * blockDim.x + threadIdx.x) >> 5;
    int lane = threadIdx.x & 31;
    int L = N * NSAMPLE;
    if (gw >= L) return;
    int W = 3 + C;

    int n = gw >> 5;
    int s = gw & (NSAMPLE - 1);
    if (s < g_cnt[n]) {
        int pos = g_off[n] + s;
        int gi  = g_ball[n * NSAMPLE + s];
        float* row = out_group + (size_t)pos * W;
        for (int c = lane; c < W; c += 32) {
            float v;
            if (c < 3) v = __fsub_rn(xyz[3 * n + c], new_xyz[3 * (size_t)gi + c]);
            else       v = feat[(size_t)n * C + (c - 3)];
            row[c] = v;
        }
        if (lane == 0 && has_idx) out_idx[pos] = (float)gi;
    }
}

// ---------------------------------------------------------------------------
extern "C" void kernel_launch(void* const* d_in, const int* in_sizes, int n_in,
                              void* d_out, int out_size) {
    const float* xyz      = (const float*)d_in[0];
    const float* new_xyz  = (const float*)d_in[2];
    const float* rois     = (const float*)d_in[3];
    const float* features = (const float*)d_in[4];

    int N  = in_sizes[0] / 3;
    int B  = in_sizes[1];
    int M  = in_sizes[3] / (7 * B);
    int K  = in_sizes[2] / (3 * B * M);
    int C  = in_sizes[4] / N;
    int Nb = N / B;
    int L  = N * NSAMPLE;
    int W  = 3 + C;

    float* out = (float*)d_out;
    int has_idx = (out_size >= L * W + L) ? 1 : 0;
    float* out_idx = out + (size_t)L * W;

    // 1. fused query (+delta stash) + per-warp absorbed zero + last-block scan
    {
        int blocks = (N + 7) / 8;          // 8 warps per 256-thread block
        query_zero_scan_kernel<<<blocks, 256>>>(
            xyz, new_xyz, rois, out, out_size, N, Nb, M, K);
    }
    // 2. valid-row gather (output already zeroed)
    if (C == 32) {
        gather35_kernel<<<(N + 7) / 8, 256>>>(features, out, out_idx, N, has_idx);
    } else {
        int blocks = (L * 32 + 255) / 256;
        gather_generic_kernel<<<blocks, 256>>>(xyz, new_xyz, features, out, out_idx,
                                               N, C, has_idx);
    }
}